// round 16
// baseline (speedup 1.0000x reference)
#include <cuda_runtime.h>
#include <cuda_fp16.h>
#include <cstdint>
#include <cstddef>

#define A_   8
#define Bsz  32768
#define EPSB 1e-5f

// ---------------- static scratch ----------------
// keys/sels/vals/atth use batch-major interleaved layout: [b][agent][128]
__device__ float g_part[8 * 32 * 160 * 2];
__device__ float g_mean[8 * 160];
__device__ float g_istd[8 * 160];
__device__ __align__(128) __half g_sah  [(size_t)A_ * Bsz * 128];   // [a][b][128]
__device__ __align__(128) __half g_keysh[(size_t)A_ * Bsz * 128];   // [b][a][128]
__device__ __align__(128) __half g_selsh[(size_t)A_ * Bsz * 128];   // [b][a][128]
__device__ __align__(128) __half g_valsh[(size_t)A_ * Bsz * 128];   // [b][a][128]
__device__ __align__(128) __half g_atth [(size_t)A_ * Bsz * 128];   // [b][a][128]
__device__ __align__(128) __half g_Benc [(size_t)8 * 128 * 160];
__device__ __align__(128) __half g_Baenc[(size_t)8 * 128 * 32];
__device__ __align__(128) __half g_Bc1  [(size_t)8 * 128 * 256];
__device__ __align__(128) __half g_Wkp[128 * 128];
__device__ __align__(128) __half g_Wsp[128 * 128];
__device__ __align__(128) __half g_Wvp[128 * 128];

__device__ __forceinline__ float lrelu(float x) { return fmaxf(x, 0.01f * x); }
__device__ __forceinline__ uint32_t smem_u32(const void* p) {
    uint32_t a;
    asm("{ .reg .u64 t; cvta.to.shared.u64 t, %1; cvt.u32.u64 %0, t; }" : "=r"(a) : "l"(p));
    return a;
}
__device__ __forceinline__ void ldsm4(uint32_t* r, uint32_t addr) {
    asm volatile("ldmatrix.sync.aligned.m8n8.x4.shared.b16 {%0,%1,%2,%3}, [%4];"
        : "=r"(r[0]), "=r"(r[1]), "=r"(r[2]), "=r"(r[3]) : "r"(addr));
}
__device__ __forceinline__ void mma16816(float* d, const uint32_t* a, const uint32_t* b) {
    asm volatile("mma.sync.aligned.m16n8k16.row.col.f32.f16.f16.f32 "
        "{%0,%1,%2,%3}, {%4,%5,%6,%7}, {%8,%9}, {%0,%1,%2,%3};"
        : "+f"(d[0]), "+f"(d[1]), "+f"(d[2]), "+f"(d[3])
        : "r"(a[0]), "r"(a[1]), "r"(a[2]), "r"(a[3]), "r"(b[0]), "r"(b[1]));
}
#define CP16(s, g) asm volatile("cp.async.cg.shared.global [%0], [%1], 16;" :: "r"(s), "l"(g))
#define CPCOMMIT() asm volatile("cp.async.commit_group;" ::: "memory")
#define CPWAIT2()  asm volatile("cp.async.wait_group 2;" ::: "memory")
#define CPWAIT1()  asm volatile("cp.async.wait_group 1;" ::: "memory")
#define CPWAIT0()  asm volatile("cp.async.wait_group 0;" ::: "memory")

__device__ __forceinline__ uint32_t pkh2(__half a, __half b) {
    __half2 h = __halves2half2(a, b);
    return *(uint32_t*)&h;
}

#define PITCH 80
#define STAGE 20480
#define CHNK  10240

// ---------------- prep: bn_partial + all weight packs, one launch ----------------
__global__ void prep_k(const float* __restrict__ states, const float* __restrict__ actions,
                       const float* __restrict__ enc_w, const float* __restrict__ aenc_w,
                       const float* __restrict__ c1_w,
                       const float* __restrict__ kw, const float* __restrict__ sw,
                       const float* __restrict__ vw) {
    __shared__ float shbuf[2048];
    int bid = blockIdx.x, t = threadIdx.x;

    if (bid < 256) {
        int a = bid >> 5, chunk = bid & 31;
        int f = t % 160, r0 = t / 160;
        size_t sb = (size_t)a * Bsz * 128, ab = (size_t)a * Bsz * 32;
        int row0 = chunk * 1024;
        float s = 0.f, s2 = 0.f;
        if (f < 128) {
            const float* p = states + sb + (size_t)(row0 + r0) * 128 + f;
            #pragma unroll 4
            for (int r = 0; r < 512; r++) { float v = *p; p += 256; s += v; s2 += v * v; }
        } else {
            const float* p = actions + ab + (size_t)(row0 + r0) * 32 + (f - 128);
            #pragma unroll 4
            for (int r = 0; r < 512; r++) { float v = *p; p += 64; s += v; s2 += v * v; }
        }
        shbuf[t] = s; shbuf[320 + t] = s2;
        __syncthreads();
        if (t < 160) {
            float ss = shbuf[t] + shbuf[t + 160];
            float qq = shbuf[320 + t] + shbuf[320 + t + 160];
            int o = ((a * 32 + chunk) * 160 + t) * 2;
            g_part[o] = ss; g_part[o + 1] = qq;
        }
        return;
    }

    int pid = bid - 256;
    const float* src; __half* dst;
    int Ksrc, mode, stride, off, a, kt;
    if (pid < 80)       { a = pid / 10; kt = pid % 10; src = enc_w;  dst = g_Benc;  Ksrc = 160; mode = 0; stride = 160; off = 0; }
    else if (pid < 96)  { int p = pid - 80;  a = p / 2; kt = p % 2; src = aenc_w; dst = g_Baenc; Ksrc = 32;  mode = 0; stride = 32;  off = 0; }
    else if (pid < 160) { int p = pid - 96;  a = p / 8; kt = p % 8; src = c1_w;   dst = g_Bc1;   Ksrc = 256; mode = 0; stride = 256; off = 0; }
    else if (pid < 224) { int p = pid - 160; a = p / 8; kt = p % 8; src = c1_w + 128 * 128; dst = g_Bc1; Ksrc = 256; mode = 0; stride = 256; off = 128; }
    else {
        int p = pid - 224; int w = p / 8; kt = p % 8; a = 0;
        src = (w == 0) ? kw : (w == 1) ? sw : vw;
        dst = (w == 0) ? g_Wkp : (w == 1) ? g_Wsp : g_Wvp;
        Ksrc = 128; mode = 1; stride = 128; off = 0;
    }
    float (*tile)[128] = (float(*)[128])shbuf;
    bool act = (t < 256);
    int k0 = kt * 16;
    if (act) {
        #pragma unroll
        for (int i = 0; i < 2; i++) {
            int p = t + i * 256;
            int kk = p >> 5, n4 = (p & 31) * 4;
            float4 v;
            if (mode == 0)
                v = *(const float4*)(src + ((size_t)a * Ksrc + k0 + kk) * 128 + n4);
            else
                v = *(const float4*)(src + ((size_t)(n4 >> 5) * 128 + k0 + kk) * 32 + (n4 & 31));
            tile[kk][n4] = v.x; tile[kk][n4 + 1] = v.y;
            tile[kk][n4 + 2] = v.z; tile[kk][n4 + 3] = v.w;
        }
    }
    __syncthreads();
    if (act) {
        #pragma unroll
        for (int i = 0; i < 2; i++) {
            int p = t + i * 256;
            int n = p >> 2, kq = p & 3;
            __half h[4];
            #pragma unroll
            for (int j = 0; j < 4; j++)
                h[j] = __float2half_rn(tile[kq * 4 + j][n]);
            uint2 u;
            u.x = pkh2(h[0], h[1]); u.y = pkh2(h[2], h[3]);
            *(uint2*)(dst + (size_t)a * 128 * stride + (size_t)n * stride
                          + off + kt * 16 + kq * 4) = u;
        }
    }
}

__global__ void bn_final_k() {
    int a = blockIdx.x, f = threadIdx.x;
    float s = 0.f, s2 = 0.f;
    for (int c = 0; c < 32; c++) {
        int o = ((a * 32 + c) * 160 + f) * 2;
        s += g_part[o]; s2 += g_part[o + 1];
    }
    float m = s * (1.f / 32768.f);
    float v = s2 * (1.f / 32768.f) - m * m;
    g_mean[a * 160 + f] = m;
    g_istd[a * 160 + f] = rsqrtf(v + EPSB);
}

// coalesced copy: fp16 tile in smem -> global, row r at gdst + r*grstride
__device__ __forceinline__ void tile_store(const char* sm, uint32_t base,
                                           uint32_t cstride, int nr,
                                           __half* gdst, size_t grstride) {
    int tid = threadIdx.x;
    int total = nr * 16;
    for (int idx = tid; idx < total; idx += 256) {
        int row = idx >> 4, c16 = idx & 15;
        uint4 v = *(const uint4*)(sm + base + (c16 >> 2) * cstride
                                  + (uint32_t)row * PITCH + (c16 & 3) * 16);
        *(uint4*)(gdst + (size_t)row * grstride + c16 * 8) = v;
    }
}

// ---------------- sa_enc + sels body ----------------
#define WSOFF 40960
__device__ __forceinline__ void sa_sels_body(
    char* sm, uint32_t smu,
    const float* __restrict__ states, const float* __restrict__ actions,
    const __half* __restrict__ Benc, const float* __restrict__ enc_b,
    const __half* __restrict__ Wsp,
    __half* __restrict__ saout, __half* __restrict__ selsout) {

    int tid = threadIdx.x, lane = tid & 31, wid = tid >> 5;
    int wm = wid & 3, wn = wid >> 2;
    int a = blockIdx.z, m0 = blockIdx.x * 128;

    #pragma unroll
    for (int i = 0; i < 8; i++) {
        int s = tid + 256 * i;
        int n = s >> 4, sr = s & 15;
        CP16(smu + WSOFF + (sr >> 2) * CHNK + n * PITCH + (sr & 3) * 16,
             Wsp + (size_t)n * 128 + sr * 8);
    }
    CPCOMMIT();

    const float* mp = g_mean + a * 160;
    const float* ip = g_istd + a * 160;
    size_t sbo = (size_t)a * Bsz * 128, abo = (size_t)a * Bsz * 32;
    const __half* Bp = Benc + (size_t)a * 128 * 160;

    float4 av[2][2];
    auto loadA = [&](int c) {
        #pragma unroll
        for (int i = 0; i < 2; i++) {
            int p = tid + i * 256;
            int row = p >> 2, kq = p & 3;
            int k = c * 32 + kq * 8;
            #pragma unroll
            for (int h = 0; h < 2; h++) {
                int kk = k + h * 4;
                float4 v;
                if (kk < 128) v = *(const float4*)(states + sbo + (size_t)(m0 + row) * 128 + kk);
                else          v = *(const float4*)(actions + abo + (size_t)(m0 + row) * 32 + (kk - 128));
                v.x = (v.x - mp[kk    ]) * ip[kk    ];
                v.y = (v.y - mp[kk + 1]) * ip[kk + 1];
                v.z = (v.z - mp[kk + 2]) * ip[kk + 2];
                v.w = (v.w - mp[kk + 3]) * ip[kk + 3];
                av[i][h] = v;
            }
        }
    };
    auto stsA = [&](int buf) {
        #pragma unroll
        for (int i = 0; i < 2; i++) {
            int p = tid + i * 256;
            int row = p >> 2, kq = p & 3;
            uint4 u;
            u.x = pkh2(__float2half_rn(av[i][0].x), __float2half_rn(av[i][0].y));
            u.y = pkh2(__float2half_rn(av[i][0].z), __float2half_rn(av[i][0].w));
            u.z = pkh2(__float2half_rn(av[i][1].x), __float2half_rn(av[i][1].y));
            u.w = pkh2(__float2half_rn(av[i][1].z), __float2half_rn(av[i][1].w));
            *(uint4*)(sm + buf * STAGE + row * PITCH + kq * 16) = u;
        }
    };
    auto cpB = [&](int c, int buf) {
        #pragma unroll
        for (int i = 0; i < 2; i++) {
            int s = tid + i * 256;
            int n = s >> 2, seg = s & 3;
            CP16(smu + buf * STAGE + CHNK + n * PITCH + seg * 16,
                 Bp + (size_t)n * 160 + c * 32 + seg * 8);
        }
    };

    int r = lane & 7, q = lane >> 3;
    uint32_t a_off[2], b_off[4], ws_off[4];
    #pragma unroll
    for (int mt = 0; mt < 2; mt++)
        a_off[mt] = (uint32_t)((wm * 32 + mt * 16 + (q & 1) * 8 + r) * PITCH + (q >> 1) * 16);
    #pragma unroll
    for (int np = 0; np < 4; np++) {
        uint32_t rb = (uint32_t)((wn * 64 + np * 16 + (q >> 1) * 8 + r) * PITCH + (q & 1) * 16);
        b_off[np]  = CHNK + rb;
        ws_off[np] = WSOFF + rb;
    }

    float acc[2][8][4];
    #pragma unroll
    for (int mt = 0; mt < 2; mt++)
        #pragma unroll
        for (int nt = 0; nt < 8; nt++)
            #pragma unroll
            for (int i = 0; i < 4; i++) acc[mt][nt][i] = 0.f;

    loadA(0); cpB(0, 0); CPCOMMIT();
    const int nch = 5;
    for (int c = 0; c < nch; c++) {
        int buf = c & 1;
        if (c + 1 < nch) { cpB(c + 1, buf ^ 1); CPCOMMIT(); }
        stsA(buf);
        if (c + 1 < nch) { loadA(c + 1); CPWAIT1(); }
        else             { CPWAIT0(); }
        __syncthreads();
        uint32_t bb = smu + buf * STAGE;
        #pragma unroll
        for (int ks = 0; ks < 2; ks++) {
            uint32_t af[2][4], bf[4][4];
            #pragma unroll
            for (int mt = 0; mt < 2; mt++) ldsm4(af[mt], bb + a_off[mt] + ks * 32);
            #pragma unroll
            for (int np = 0; np < 4; np++) ldsm4(bf[np], bb + b_off[np] + ks * 32);
            #pragma unroll
            for (int mt = 0; mt < 2; mt++)
                #pragma unroll
                for (int nt = 0; nt < 8; nt++)
                    mma16816(acc[mt][nt], af[mt], &bf[nt >> 1][(nt & 1) * 2]);
        }
        __syncthreads();
    }

    int g = lane >> 2, tig = lane & 3;

    #pragma unroll
    for (int mt = 0; mt < 2; mt++) {
        int row = wm * 32 + mt * 16 + g;
        #pragma unroll
        for (int nt = 0; nt < 8; nt++) {
            int col = wn * 64 + nt * 8 + 2 * tig;
            float b0 = enc_b[a * 128 + col], b1 = enc_b[a * 128 + col + 1];
            float v0 = lrelu(acc[mt][nt][0] + b0), v1 = lrelu(acc[mt][nt][1] + b1);
            float v2 = lrelu(acc[mt][nt][2] + b0), v3 = lrelu(acc[mt][nt][3] + b1);
            uint32_t tadr = (uint32_t)((col >> 5) * CHNK + row * PITCH + (col & 31) * 2);
            *(__half2*)(sm + tadr)             = __floats2half2_rn(v0, v1);
            *(__half2*)(sm + tadr + 8 * PITCH) = __floats2half2_rn(v2, v3);
        }
    }
    __syncthreads();

    // sa: [a][b][128] layout, row stride 128
    tile_store(sm, 0, CHNK, 128, saout + ((size_t)a * Bsz + m0) * 128, 128);

    float a2[2][8][4];
    #pragma unroll
    for (int mt = 0; mt < 2; mt++)
        #pragma unroll
        for (int nt = 0; nt < 8; nt++)
            #pragma unroll
            for (int i = 0; i < 4; i++) a2[mt][nt][i] = 0.f;
    #pragma unroll
    for (int ks = 0; ks < 8; ks++) {
        uint32_t coff = (uint32_t)((ks >> 1) * CHNK + (ks & 1) * 32);
        uint32_t af[2][4], bf[4][4];
        #pragma unroll
        for (int mt = 0; mt < 2; mt++) ldsm4(af[mt], smu + a_off[mt] + coff);
        #pragma unroll
        for (int np = 0; np < 4; np++) ldsm4(bf[np], smu + ws_off[np] + coff);
        #pragma unroll
        for (int mt = 0; mt < 2; mt++)
            #pragma unroll
            for (int nt = 0; nt < 8; nt++)
                mma16816(a2[mt][nt], af[mt], &bf[nt >> 1][(nt & 1) * 2]);
    }
    __syncthreads();
    #pragma unroll
    for (int mt = 0; mt < 2; mt++) {
        int row = wm * 32 + mt * 16 + g;
        #pragma unroll
        for (int nt = 0; nt < 8; nt++) {
            int col = wn * 64 + nt * 8 + 2 * tig;
            uint32_t tadr = (uint32_t)(WSOFF + (col >> 5) * CHNK + row * PITCH + (col & 31) * 2);
            *(__half2*)(sm + tadr)             = __floats2half2_rn(a2[mt][nt][0], a2[mt][nt][1]);
            *(__half2*)(sm + tadr + 8 * PITCH) = __floats2half2_rn(a2[mt][nt][2], a2[mt][nt][3]);
        }
    }
    __syncthreads();
    // sels: [b][a][128] layout, row stride 8*128=1024
    tile_store(sm, WSOFF, CHNK, 128, selsout + ((size_t)m0 * 8 + a) * 128, 1024);
}

// ---------------- a_enc + keys + vals body ----------------
#define BSOFF 40960
#define KVST  61440
#define KVCH  5120
__device__ __forceinline__ void aenc_kv_body(
    char* sm, uint32_t smu,
    const float* __restrict__ actions,
    const __half* __restrict__ Baenc, const float* __restrict__ aenc_b,
    const __half* __restrict__ Wkp, const __half* __restrict__ Wvp,
    const float* __restrict__ valb,
    __half* __restrict__ keysh, __half* __restrict__ valsh) {

    int tid = threadIdx.x, lane = tid & 31, wid = tid >> 5;
    int wm = wid & 3, wn = wid >> 2;
    int a = blockIdx.z, m0 = blockIdx.x * 128;

    const float* mp = g_mean + a * 160;
    const float* ip = g_istd + a * 160;
    size_t abo = (size_t)a * Bsz * 32;
    const __half* Bp = Baenc + (size_t)a * 128 * 32;

    #pragma unroll
    for (int i = 0; i < 2; i++) {
        int s = tid + i * 256;
        int n = s >> 2, seg = s & 3;
        CP16(smu + BSOFF + n * PITCH + seg * 16, Wkp + (size_t)n * 128 + seg * 8);
    }
    CPCOMMIT();

    float4 av[2][2];
    #pragma unroll
    for (int i = 0; i < 2; i++) {
        int p = tid + i * 256;
        int row = p >> 2, kq = p & 3;
        #pragma unroll
        for (int h = 0; h < 2; h++) {
            int kk = kq * 8 + h * 4;
            float4 v = *(const float4*)(actions + abo + (size_t)(m0 + row) * 32 + kk);
            v.x = (v.x - mp[128 + kk]) * ip[128 + kk];
            v.y = (v.y - mp[129 + kk]) * ip[129 + kk];
            v.z = (v.z - mp[130 + kk]) * ip[130 + kk];
            v.w = (v.w - mp[131 + kk]) * ip[131 + kk];
            av[i][h] = v;
        }
    }
    #pragma unroll
    for (int i = 0; i < 2; i++) {
        int s = tid + i * 256;
        int n = s >> 2, seg = s & 3;
        CP16(smu + CHNK + n * PITCH + seg * 16, Bp + (size_t)n * 32 + seg * 8);
    }
    CPCOMMIT();
    #pragma unroll
    for (int i = 0; i < 2; i++) {
        int p = tid + i * 256;
        int row = p >> 2, kq = p & 3;
        uint4 u;
        u.x = pkh2(__float2half_rn(av[i][0].x), __float2half_rn(av[i][0].y));
        u.y = pkh2(__float2half_rn(av[i][0].z), __float2half_rn(av[i][0].w));
        u.z = pkh2(__float2half_rn(av[i][1].x), __float2half_rn(av[i][1].y));
        u.w = pkh2(__float2half_rn(av[i][1].z), __float2half_rn(av[i][1].w));
        *(uint4*)(sm + row * PITCH + kq * 16) = u;
    }
    CPWAIT0();
    __syncthreads();

    int r = lane & 7, q = lane >> 3;
    uint32_t a_off[2], b_off[4], bs_off[4];
    #pragma unroll
    for (int mt = 0; mt < 2; mt++)
        a_off[mt] = (uint32_t)((wm * 32 + mt * 16 + (q & 1) * 8 + r) * PITCH + (q >> 1) * 16);
    #pragma unroll
    for (int np = 0; np < 4; np++) {
        uint32_t rb = (uint32_t)((wn * 64 + np * 16 + (q >> 1) * 8 + r) * PITCH + (q & 1) * 16);
        b_off[np]  = CHNK + rb;
        bs_off[np] = BSOFF + rb;
    }

    float acc[2][8][4];
    #pragma unroll
    for (int mt = 0; mt < 2; mt++)
        #pragma unroll
        for (int nt = 0; nt < 8; nt++)
            #pragma unroll
            for (int i = 0; i < 4; i++) acc[mt][nt][i] = 0.f;

    #pragma unroll
    for (int ks = 0; ks < 2; ks++) {
        uint32_t af[2][4], bf[4][4];
        #pragma unroll
        for (int mt = 0; mt < 2; mt++) ldsm4(af[mt], smu + a_off[mt] + ks * 32);
        #pragma unroll
        for (int np = 0; np < 4; np++) ldsm4(bf[np], smu + b_off[np] + ks * 32);
        #pragma unroll
        for (int mt = 0; mt < 2; mt++)
            #pragma unroll
            for (int nt = 0; nt < 8; nt++)
                mma16816(acc[mt][nt], af[mt], &bf[nt >> 1][(nt & 1) * 2]);
    }
    __syncthreads();

    int g = lane >> 2, tig = lane & 3;

    #pragma unroll
    for (int mt = 0; mt < 2; mt++) {
        int row = wm * 32 + mt * 16 + g;
        #pragma unroll
        for (int nt = 0; nt < 8; nt++) {
            int col = wn * 64 + nt * 8 + 2 * tig;
            float b0 = aenc_b[a * 128 + col], b1 = aenc_b[a * 128 + col + 1];
            float v0 = lrelu(acc[mt][nt][0] + b0), v1 = lrelu(acc[mt][nt][1] + b1);
            float v2 = lrelu(acc[mt][nt][2] + b0), v3 = lrelu(acc[mt][nt][3] + b1);
            uint32_t tadr = (uint32_t)((col >> 5) * CHNK + row * PITCH + (col & 31) * 2);
            *(__half2*)(sm + tadr)             = __floats2half2_rn(v0, v1);
            *(__half2*)(sm + tadr + 8 * PITCH) = __floats2half2_rn(v2, v3);
            acc[mt][nt][0] = 0.f; acc[mt][nt][1] = 0.f;
            acc[mt][nt][2] = 0.f; acc[mt][nt][3] = 0.f;
        }
    }
    __syncthreads();

    auto cpB2 = [&](int c, int buf) {
        const __half* src = (c < 4) ? Wkp : Wvp;
        int cc = c & 3;
        #pragma unroll
        for (int i = 0; i < 2; i++) {
            int s = tid + i * 256;
            int n = s >> 2, seg = s & 3;
            CP16(smu + BSOFF + buf * CHNK + n * PITCH + seg * 16,
                 src + (size_t)n * 128 + cc * 32 + seg * 8);
        }
    };

    for (int c = 0; c < 8; c++) {
        int buf = c & 1;
        if (c + 1 < 8) { cpB2(c + 1, buf ^ 1); CPCOMMIT(); CPWAIT1(); }
        else           { CPWAIT0(); }
        __syncthreads();
        #pragma unroll
        for (int ks = 0; ks < 2; ks++) {
            uint32_t coffA = (uint32_t)((c & 3) * CHNK + ks * 32);
            uint32_t af[2][4], bf[4][4];
            #pragma unroll
            for (int mt = 0; mt < 2; mt++) ldsm4(af[mt], smu + a_off[mt] + coffA);
            #pragma unroll
            for (int np = 0; np < 4; np++) ldsm4(bf[np], smu + bs_off[np] + buf * CHNK + ks * 32);
            #pragma unroll
            for (int mt = 0; mt < 2; mt++)
                #pragma unroll
                for (int nt = 0; nt < 8; nt++)
                    mma16816(acc[mt][nt], af[mt], &bf[nt >> 1][(nt & 1) * 2]);
        }
        __syncthreads();

        if (c == 3 || c == 7) {
            bool isv = (c == 7);
            __half* outp = isv ? valsh : keysh;
            #pragma unroll
            for (int pass = 0; pass < 2; pass++) {
                if ((wm >> 1) == pass) {
                    int lbase = (wm & 1) * 32;
                    #pragma unroll
                    for (int mt = 0; mt < 2; mt++) {
                        int lrow = lbase + mt * 16 + g;
                        #pragma unroll
                        for (int nt = 0; nt < 8; nt++) {
                            int col = wn * 64 + nt * 8 + 2 * tig;
                            float v0 = acc[mt][nt][0], v1 = acc[mt][nt][1];
                            float v2 = acc[mt][nt][2], v3 = acc[mt][nt][3];
                            if (isv) {
                                float b0 = valb[col], b1 = valb[col + 1];
                                v0 = lrelu(v0 + b0); v1 = lrelu(v1 + b1);
                                v2 = lrelu(v2 + b0); v3 = lrelu(v3 + b1);
                            }
                            uint32_t tadr = (uint32_t)(KVST + (col >> 5) * KVCH
                                            + lrow * PITCH + (col & 31) * 2);
                            *(__half2*)(sm + tadr)             = __floats2half2_rn(v0, v1);
                            *(__half2*)(sm + tadr + 8 * PITCH) = __floats2half2_rn(v2, v3);
                        }
                    }
                }
                __syncthreads();
                // keys/vals: [b][a][128], row stride 1024
                tile_store(sm, KVST, KVCH, 64,
                           outp + ((size_t)(m0 + pass * 64) * 8 + a) * 128, 1024);
                __syncthreads();
            }
            if (!isv) {
                #pragma unroll
                for (int mt = 0; mt < 2; mt++)
                    #pragma unroll
                    for (int nt = 0; nt < 8; nt++)
                        #pragma unroll
                        for (int i = 0; i < 4; i++) acc[mt][nt][i] = 0.f;
            }
        }
    }
}

// ---------------- merged encoder launch ----------------
__global__ __launch_bounds__(256, 2) void enc_k(
    const float* __restrict__ states, const float* __restrict__ actions,
    const __half* __restrict__ Benc, const float* __restrict__ enc_b,
    const __half* __restrict__ Wsp,
    __half* __restrict__ saout, __half* __restrict__ selsout,
    const __half* __restrict__ Baenc, const float* __restrict__ aenc_b,
    const __half* __restrict__ Wkp, const __half* __restrict__ Wvp,
    const float* __restrict__ valb,
    __half* __restrict__ keysh, __half* __restrict__ valsh) {

    extern __shared__ __align__(16) char sm[];
    uint32_t smu = smem_u32(sm);
    if (blockIdx.y == 0)
        sa_sels_body(sm, smu, states, actions, Benc, enc_b, Wsp, saout, selsout);
    else
        aenc_kv_body(sm, smu, actions, Baenc, aenc_b, Wkp, Wvp, valb, keysh, valsh);
}

// ---------------- c1 + q fused, PDL-split ----------------
__global__ __launch_bounds__(256, 2) void c1q_k(
    const __half* __restrict__ sah, const __half* __restrict__ att,
    const __half* __restrict__ Bc1, const float* __restrict__ c1_b,
    const float* __restrict__ c2w, const float* __restrict__ c2b,
    float* __restrict__ qout) {

    extern __shared__ __align__(16) char sm[];
    uint32_t smu = smem_u32(sm);
    int tid = threadIdx.x, lane = tid & 31, wid = tid >> 5;
    int wm = wid & 3, wn = wid >> 2;
    int a = blockIdx.z, m0 = blockIdx.x * 128;

    const char* Ap  = (const char*)(sah + (size_t)a * Bsz * 128);
    const char* Atp = (const char*)att;   // [b][a][128]
    const __half* Bpp = Bc1 + (size_t)a * 128 * 256;

    auto cpA = [&](int c, int buf) {
        #pragma unroll
        for (int i = 0; i < 2; i++) {
            int p = tid + i * 256;
            int row = p >> 2, seg = p & 3;
            const char* g;
            if (c < 4) g = Ap + (size_t)(m0 + row) * 256 + c * 64 + seg * 16;
            else       g = Atp + ((size_t)(m0 + row) * 8 + a) * 256 + (c - 4) * 64 + seg * 16;
            CP16(smu + buf * STAGE + row * PITCH + seg * 16, g);
        }
    };
    auto cpB = [&](int c, int buf) {
        #pragma unroll
        for (int i = 0; i < 2; i++) {
            int s = tid + i * 256;
            int n = s >> 2, seg = s & 3;
            CP16(smu + buf * STAGE + CHNK + n * PITCH + seg * 16,
                 Bpp + (size_t)n * 256 + c * 32 + seg * 8);
        }
    };

    int r = lane & 7, q = lane >> 3;
    uint32_t a_off[2], b_off[4];
    #pragma unroll
    for (int mt = 0; mt < 2; mt++)
        a_off[mt] = (uint32_t)((wm * 32 + mt * 16 + (q & 1) * 8 + r) * PITCH + (q >> 1) * 16);
    #pragma unroll
    for (int np = 0; np < 4; np++)
        b_off[np] = (uint32_t)(CHNK + (wn * 64 + np * 16 + (q >> 1) * 8 + r) * PITCH + (q & 1) * 16);

    float acc[2][8][4];
    #pragma unroll
    for (int mt = 0; mt < 2; mt++)
        #pragma unroll
        for (int nt = 0; nt < 8; nt++)
            #pragma unroll
            for (int i = 0; i < 4; i++) acc[mt][nt][i] = 0.f;

    auto run_phase = [&](int lo) {
        cpA(lo, 0); cpB(lo, 0); CPCOMMIT();
        cpA(lo + 1, 1); cpB(lo + 1, 1); CPCOMMIT();
        int buf = 0;
        #pragma unroll
        for (int cc = 0; cc < 4; cc++) {
            int c = lo + cc;
            if (cc + 2 < 4) {
                int nb = (buf + 2) % 3;
                cpA(c + 2, nb); cpB(c + 2, nb); CPCOMMIT();
                CPWAIT2();
            } else if (cc + 1 < 4) {
                CPWAIT1();
            } else {
                CPWAIT0();
            }
            __syncthreads();
            uint32_t bb = smu + buf * STAGE;
            #pragma unroll
            for (int ks = 0; ks < 2; ks++) {
                uint32_t af[2][4], bf[4][4];
                #pragma unroll
                for (int mt = 0; mt < 2; mt++) ldsm4(af[mt], bb + a_off[mt] + ks * 32);
                #pragma unroll
                for (int np = 0; np < 4; np++) ldsm4(bf[np], bb + b_off[np] + ks * 32);
                #pragma unroll
                for (int mt = 0; mt < 2; mt++)
                    #pragma unroll
                    for (int nt = 0; nt < 8; nt++)
                        mma16816(acc[mt][nt], af[mt], &bf[nt >> 1][(nt & 1) * 2]);
            }
            __syncthreads();
            buf = (buf + 1) % 3;
        }
    };

    run_phase(0);
    cudaGridDependencySynchronize();
    run_phase(4);

    int g = lane >> 2, tig = lane & 3;
    float qp[4] = {0.f, 0.f, 0.f, 0.f};
    #pragma unroll
    for (int mt = 0; mt < 2; mt++)
        #pragma unroll
        for (int nt = 0; nt < 8; nt++) {
            int col = wn * 64 + nt * 8 + 2 * tig;
            float b0 = c1_b[a * 128 + col], b1 = c1_b[a * 128 + col + 1];
            float w0 = c2w[a * 128 + col], w1 = c2w[a * 128 + col + 1];
            qp[mt * 2]     += lrelu(acc[mt][nt][0] + b0) * w0 + lrelu(acc[mt][nt][1] + b1) * w1;
            qp[mt * 2 + 1] += lrelu(acc[mt][nt][2] + b0) * w0 + lrelu(acc[mt][nt][3] + b1) * w1;
        }
    #pragma unroll
    for (int j = 0; j < 4; j++) {
        qp[j] += __shfl_xor_sync(0xffffffffu, qp[j], 1);
        qp[j] += __shfl_xor_sync(0xffffffffu, qp[j], 2);
    }
    __syncthreads();
    float* qsm = (float*)sm;
    if (tig == 0) {
        #pragma unroll
        for (int j = 0; j < 4; j++) {
            int rl = wm * 32 + (j >> 1) * 16 + (j & 1) * 8 + g;
            qsm[rl * 2 + wn] = qp[j];
        }
    }
    __syncthreads();
    if (tid < 128)
        qout[(size_t)a * Bsz + m0 + tid] = qsm[tid * 2] + qsm[tid * 2 + 1] + c2b[a];
}

// ---------------- attention: batch-major layout, contiguous windows ----------
#define APITCH 36
__global__ __launch_bounds__(128) void attn_k() {
    cudaTriggerProgrammaticLaunchCompletion();

    __shared__ __half sS[128 * APITCH];
    __shared__ __half sK[128 * APITCH];
    int t = threadIdx.x;
    int b0 = blockIdx.x * 16;
    int bl = t >> 3, iq = t & 7;

    for (int kh = 0; kh < 4; kh++) {
        __syncthreads();
        {
            int lbl = t >> 3, ag = t & 7;
            size_t off = ((size_t)(b0 + lbl) * 8 + ag) * 128 + kh * 32;
            const uint2* ps = (const uint2*)(g_selsh + off);
            const uint2* pk = (const uint2*)(g_keysh + off);
            uint2* ds = (uint2*)(sS + (lbl * 8 + ag) * APITCH);
            uint2* dk = (uint2*)(sK + (lbl * 8 + ag) * APITCH);
            #pragma unroll
            for (int j = 0; j < 8; j++) { ds[j] = ps[j]; dk[j] = pk[j]; }
        }
        __syncthreads();

        float sv[32];
        {
            const __half2* p = (const __half2*)(sS + (bl * 8 + iq) * APITCH);
            #pragma unroll
            for (int d = 0; d < 16; d++) {
                float2 f = __half22float2(p[d]);
                sv[2 * d] = f.x; sv[2 * d + 1] = f.y;
            }
        }
        float pj[8];
        #pragma unroll
        for (int j = 0; j < 8; j++) {
            const __half2* p = (const __half2*)(sK + (bl * 8 + j) * APITCH);
            float acc = 0.f;
            #pragma unroll
            for (int d = 0; d < 16; d++) {
                float2 f = __half22float2(p[d]);
                acc += sv[2 * d] * f.x + sv[2 * d + 1] * f.y;
            }
            pj[j] = acc * 0.17677669529663687f;
        }
        float mx = -1e30f;
        #pragma unroll
        for (int j = 0; j < 8; j++) if (j != iq) mx = fmaxf(mx, pj[j]);
        float sum = 0.f;
        #pragma unroll
        for (int j = 0; j < 8; j++) {
            pj[j] = (j == iq) ? 0.f : __expf(pj[j] - mx);
            sum += pj[j];
        }
        float inv = 1.f / sum;

        __syncthreads();
        {
            int lbl = t >> 3, ag = t & 7;
            size_t off = ((size_t)(b0 + lbl) * 8 + ag) * 128 + kh * 32;
            const uint2* pv = (const uint2*)(g_valsh + off);
            uint2* ds = (uint2*)(sS + (lbl * 8 + ag) * APITCH);
            #pragma unroll
            for (int j = 0; j < 8; j++) ds[j] = pv[j];
        }
        __syncthreads();

        float ov[32];
        #pragma unroll
        for (int d = 0; d < 32; d++) ov[d] = 0.f;
        #pragma unroll
        for (int j = 0; j < 8; j++) {
            float w = pj[j] * inv;
            const __half2* p = (const __half2*)(sS + (bl * 8 + j) * APITCH);
            #pragma unroll
            for (int d = 0; d < 16; d++) {
                float2 f = __half22float2(p[d]);
                ov[2 * d]     += w * f.x;
                ov[2 * d + 1] += w * f.y;
            }
        }
        __half* dst = g_atth + ((size_t)(b0 + bl) * 8 + iq) * 128 + kh * 32;
        #pragma unroll
        for (int d4 = 0; d4 < 4; d4++) {
            __half2 h0 = __floats2half2_rn(ov[d4 * 8 + 0], ov[d4 * 8 + 1]);
            __half2 h1 = __floats2half2_rn(ov[d4 * 8 + 2], ov[d4 * 8 + 3]);
            __half2 h2 = __floats2half2_rn(ov[d4 * 8 + 4], ov[d4 * 8 + 5]);
            __half2 h3 = __floats2half2_rn(ov[d4 * 8 + 6], ov[d4 * 8 + 7]);
            uint4 u;
            u.x = *(uint32_t*)&h0; u.y = *(uint32_t*)&h1;
            u.z = *(uint32_t*)&h2; u.w = *(uint32_t*)&h3;
            *(uint4*)(dst + d4 * 8) = u;
        }
    }
}

// ---------------- launch ----------------
extern "C" void kernel_launch(void* const* d_in, const int* in_sizes, int n_in,
                              void* d_out, int out_size) {
    const float* states = (const float*)d_in[0];
    const float* actions= (const float*)d_in[1];
    const float* enc_w  = (const float*)d_in[2];
    const float* enc_b  = (const float*)d_in[3];
    const float* aenc_w = (const float*)d_in[4];
    const float* aenc_b = (const float*)d_in[5];
    const float* key_w  = (const float*)d_in[6];
    const float* sel_w  = (const float*)d_in[7];
    const float* val_w  = (const float*)d_in[8];
    const float* val_b  = (const float*)d_in[9];
    const float* c1_w   = (const float*)d_in[10];
    const float* c1_b   = (const float*)d_in[11];
    const float* c2_w   = (const float*)d_in[12];
    const float* c2_b   = (const float*)d_in[13];
    float* out = (float*)d_out;

    void *p_sah, *p_keysh, *p_selsh, *p_valsh, *p_atth;
    void *p_Benc, *p_Baenc, *p_Bc1, *p_Wkp, *p_Wsp, *p_Wvp;
    cudaGetSymbolAddress(&p_sah,  g_sah);
    cudaGetSymbolAddress(&p_keysh,g_keysh);
    cudaGetSymbolAddress(&p_selsh,g_selsh);
    cudaGetSymbolAddress(&p_valsh,g_valsh);
    cudaGetSymbolAddress(&p_atth, g_atth);
    cudaGetSymbolAddress(&p_Benc, g_Benc);
    cudaGetSymbolAddress(&p_Baenc,g_Baenc);
    cudaGetSymbolAddress(&p_Bc1,  g_Bc1);
    cudaGetSymbolAddress(&p_Wkp,  g_Wkp);
    cudaGetSymbolAddress(&p_Wsp,  g_Wsp);
    cudaGetSymbolAddress(&p_Wvp,  g_Wvp);

    cudaFuncSetAttribute(enc_k, cudaFuncAttributeMaxDynamicSharedMemorySize, 81920);
    cudaFuncSetAttribute(c1q_k, cudaFuncAttributeMaxDynamicSharedMemorySize, 61440);

    prep_k<<<504, 320>>>(states, actions, enc_w, aenc_w, c1_w, key_w, sel_w, val_w);
    bn_final_k<<<8, 160>>>();
    enc_k<<<dim3(256, 2, 8), 256, 81920>>>(
        states, actions,
        (const __half*)p_Benc, enc_b, (const __half*)p_Wsp,
        (__half*)p_sah, (__half*)p_selsh,
        (const __half*)p_Baenc, aenc_b,
        (const __half*)p_Wkp, (const __half*)p_Wvp, val_b,
        (__half*)p_keysh, (__half*)p_valsh);
    attn_k<<<Bsz / 16, 128>>>();

    {
        cudaLaunchConfig_t cfg = {};
        cfg.gridDim = dim3(256, 1, 8);
        cfg.blockDim = dim3(256, 1, 1);
        cfg.dynamicSmemBytes = 61440;
        cfg.stream = 0;
        cudaLaunchAttribute at[1];
        at[0].id = cudaLaunchAttributeProgrammaticStreamSerialization;
        at[0].val.programmaticStreamSerializationAllowed = 1;
        cfg.attrs = at;
        cfg.numAttrs = 1;
        cudaLaunchKernelEx(&cfg, c1q_k,
                           (const __half*)p_sah, (const __half*)p_atth,
                           (const __half*)p_Bc1, c1_b, c2_w, c2_b, out);
    }
}

// round 17
// speedup vs baseline: 1.0301x; 1.0301x over previous
#include <cuda_runtime.h>
#include <cuda_fp16.h>
#include <cstdint>
#include <cstddef>

#define A_   8
#define Bsz  32768
#define EPSB 1e-5f

__device__ float g_part[8 * 32 * 160 * 2];
__device__ float g_mean[8 * 160];
__device__ float g_istd[8 * 160];
__device__ __align__(128) __half g_sah  [(size_t)A_ * Bsz * 128];
__device__ __align__(128) __half g_keysh[(size_t)A_ * Bsz * 128];
__device__ __align__(128) __half g_selsh[(size_t)A_ * Bsz * 128];
__device__ __align__(128) __half g_valsh[(size_t)A_ * Bsz * 128];
__device__ __align__(128) __half g_atth [(size_t)A_ * Bsz * 128];
__device__ __align__(128) __half g_Benc [(size_t)8 * 128 * 160];
__device__ __align__(128) __half g_Baenc[(size_t)8 * 128 * 32];
__device__ __align__(128) __half g_Bc1  [(size_t)8 * 128 * 256];
__device__ __align__(128) __half g_Wkp[128 * 128];
__device__ __align__(128) __half g_Wsp[128 * 128];
__device__ __align__(128) __half g_Wvp[128 * 128];

__device__ __forceinline__ float lrelu(float x) { return fmaxf(x, 0.01f * x); }
__device__ __forceinline__ uint32_t smem_u32(const void* p) {
    uint32_t a;
    asm("{ .reg .u64 t; cvta.to.shared.u64 t, %1; cvt.u32.u64 %0, t; }" : "=r"(a) : "l"(p));
    return a;
}
__device__ __forceinline__ void ldsm4(uint32_t* r, uint32_t addr) {
    asm volatile("ldmatrix.sync.aligned.m8n8.x4.shared.b16 {%0,%1,%2,%3}, [%4];"
        : "=r"(r[0]), "=r"(r[1]), "=r"(r[2]), "=r"(r[3]) : "r"(addr));
}
__device__ __forceinline__ void mma16816(float* d, const uint32_t* a, const uint32_t* b) {
    asm volatile("mma.sync.aligned.m16n8k16.row.col.f32.f16.f16.f32 "
        "{%0,%1,%2,%3}, {%4,%5,%6,%7}, {%8,%9}, {%0,%1,%2,%3};"
        : "+f"(d[0]), "+f"(d[1]), "+f"(d[2]), "+f"(d[3])
        : "r"(a[0]), "r"(a[1]), "r"(a[2]), "r"(a[3]), "r"(b[0]), "r"(b[1]));
}
#define CP16(s, g) asm volatile("cp.async.cg.shared.global [%0], [%1], 16;" :: "r"(s), "l"(g))
#define CPCOMMIT() asm volatile("cp.async.commit_group;" ::: "memory")
#define CPWAIT2()  asm volatile("cp.async.wait_group 2;" ::: "memory")
#define CPWAIT1()  asm volatile("cp.async.wait_group 1;" ::: "memory")
#define CPWAIT0()  asm volatile("cp.async.wait_group 0;" ::: "memory")

__device__ __forceinline__ uint32_t pkh2(__half a, __half b) {
    __half2 h = __halves2half2(a, b);
    return *(uint32_t*)&h;
}

#define PITCH 80
#define STAGE 20480
#define CHNK  10240

// ---------------- prep: bn_partial + all weight packs, one launch ----------------
__global__ void prep_k(const float* __restrict__ states, const float* __restrict__ actions,
                       const float* __restrict__ enc_w, const float* __restrict__ aenc_w,
                       const float* __restrict__ c1_w,
                       const float* __restrict__ kw, const float* __restrict__ sw,
                       const float* __restrict__ vw) {
    __shared__ float shbuf[2048];
    int bid = blockIdx.x, t = threadIdx.x;

    if (bid < 256) {
        int a = bid >> 5, chunk = bid & 31;
        int f = t % 160, r0 = t / 160;
        size_t sb = (size_t)a * Bsz * 128, ab = (size_t)a * Bsz * 32;
        int row0 = chunk * 1024;
        float s = 0.f, s2 = 0.f;
        if (f < 128) {
            const float* p = states + sb + (size_t)(row0 + r0) * 128 + f;
            #pragma unroll 4
            for (int r = 0; r < 512; r++) { float v = *p; p += 256; s += v; s2 += v * v; }
        } else {
            const float* p = actions + ab + (size_t)(row0 + r0) * 32 + (f - 128);
            #pragma unroll 4
            for (int r = 0; r < 512; r++) { float v = *p; p += 64; s += v; s2 += v * v; }
        }
        shbuf[t] = s; shbuf[320 + t] = s2;
        __syncthreads();
        if (t < 160) {
            float ss = shbuf[t] + shbuf[t + 160];
            float qq = shbuf[320 + t] + shbuf[320 + t + 160];
            int o = ((a * 32 + chunk) * 160 + t) * 2;
            g_part[o] = ss; g_part[o + 1] = qq;
        }
        return;
    }

    int pid = bid - 256;
    const float* src; __half* dst;
    int Ksrc, mode, stride, off, a, kt;
    if (pid < 80)       { a = pid / 10; kt = pid % 10; src = enc_w;  dst = g_Benc;  Ksrc = 160; mode = 0; stride = 160; off = 0; }
    else if (pid < 96)  { int p = pid - 80;  a = p / 2; kt = p % 2; src = aenc_w; dst = g_Baenc; Ksrc = 32;  mode = 0; stride = 32;  off = 0; }
    else if (pid < 160) { int p = pid - 96;  a = p / 8; kt = p % 8; src = c1_w;   dst = g_Bc1;   Ksrc = 256; mode = 0; stride = 256; off = 0; }
    else if (pid < 224) { int p = pid - 160; a = p / 8; kt = p % 8; src = c1_w + 128 * 128; dst = g_Bc1; Ksrc = 256; mode = 0; stride = 256; off = 128; }
    else {
        int p = pid - 224; int w = p / 8; kt = p % 8; a = 0;
        src = (w == 0) ? kw : (w == 1) ? sw : vw;
        dst = (w == 0) ? g_Wkp : (w == 1) ? g_Wsp : g_Wvp;
        Ksrc = 128; mode = 1; stride = 128; off = 0;
    }
    float (*tile)[128] = (float(*)[128])shbuf;
    bool act = (t < 256);
    int k0 = kt * 16;
    if (act) {
        #pragma unroll
        for (int i = 0; i < 2; i++) {
            int p = t + i * 256;
            int kk = p >> 5, n4 = (p & 31) * 4;
            float4 v;
            if (mode == 0)
                v = *(const float4*)(src + ((size_t)a * Ksrc + k0 + kk) * 128 + n4);
            else
                v = *(const float4*)(src + ((size_t)(n4 >> 5) * 128 + k0 + kk) * 32 + (n4 & 31));
            tile[kk][n4] = v.x; tile[kk][n4 + 1] = v.y;
            tile[kk][n4 + 2] = v.z; tile[kk][n4 + 3] = v.w;
        }
    }
    __syncthreads();
    if (act) {
        #pragma unroll
        for (int i = 0; i < 2; i++) {
            int p = t + i * 256;
            int n = p >> 2, kq = p & 3;
            __half h[4];
            #pragma unroll
            for (int j = 0; j < 4; j++)
                h[j] = __float2half_rn(tile[kq * 4 + j][n]);
            uint2 u;
            u.x = pkh2(h[0], h[1]); u.y = pkh2(h[2], h[3]);
            *(uint2*)(dst + (size_t)a * 128 * stride + (size_t)n * stride
                          + off + kt * 16 + kq * 4) = u;
        }
    }
}

__global__ void bn_final_k() {
    int a = blockIdx.x, f = threadIdx.x;
    float s = 0.f, s2 = 0.f;
    for (int c = 0; c < 32; c++) {
        int o = ((a * 32 + c) * 160 + f) * 2;
        s += g_part[o]; s2 += g_part[o + 1];
    }
    float m = s * (1.f / 32768.f);
    float v = s2 * (1.f / 32768.f) - m * m;
    g_mean[a * 160 + f] = m;
    g_istd[a * 160 + f] = rsqrtf(v + EPSB);
}

// coalesced copy: fp16 tile in smem -> global row-major [row][128]
__device__ __forceinline__ void tile_store(const char* sm, uint32_t base,
                                           uint32_t cstride, int nr,
                                           __half* gdst, size_t grow0) {
    int tid = threadIdx.x;
    int total = nr * 16;
    for (int idx = tid; idx < total; idx += 256) {
        int row = idx >> 4, c16 = idx & 15;
        uint4 v = *(const uint4*)(sm + base + (c16 >> 2) * cstride
                                  + (uint32_t)row * PITCH + (c16 & 3) * 16);
        *(uint4*)(gdst + (grow0 + row) * 128 + c16 * 8) = v;
    }
}

// ---------------- sa_enc + sels body ----------------
#define WSOFF 40960
__device__ __forceinline__ void sa_sels_body(
    char* sm, uint32_t smu,
    const float* __restrict__ states, const float* __restrict__ actions,
    const __half* __restrict__ Benc, const float* __restrict__ enc_b,
    const __half* __restrict__ Wsp,
    __half* __restrict__ saout, __half* __restrict__ selsout) {

    int tid = threadIdx.x, lane = tid & 31, wid = tid >> 5;
    int wm = wid & 3, wn = wid >> 2;
    int a = blockIdx.z, m0 = blockIdx.x * 128;

    #pragma unroll
    for (int i = 0; i < 8; i++) {
        int s = tid + 256 * i;
        int n = s >> 4, sr = s & 15;
        CP16(smu + WSOFF + (sr >> 2) * CHNK + n * PITCH + (sr & 3) * 16,
             Wsp + (size_t)n * 128 + sr * 8);
    }
    CPCOMMIT();

    const float* mp = g_mean + a * 160;
    const float* ip = g_istd + a * 160;
    size_t sbo = (size_t)a * Bsz * 128, abo = (size_t)a * Bsz * 32;
    const __half* Bp = Benc + (size_t)a * 128 * 160;

    float4 av[2][2];
    auto loadA = [&](int c) {
        #pragma unroll
        for (int i = 0; i < 2; i++) {
            int p = tid + i * 256;
            int row = p >> 2, kq = p & 3;
            int k = c * 32 + kq * 8;
            #pragma unroll
            for (int h = 0; h < 2; h++) {
                int kk = k + h * 4;
                float4 v;
                if (kk < 128) v = *(const float4*)(states + sbo + (size_t)(m0 + row) * 128 + kk);
                else          v = *(const float4*)(actions + abo + (size_t)(m0 + row) * 32 + (kk - 128));
                v.x = (v.x - mp[kk    ]) * ip[kk    ];
                v.y = (v.y - mp[kk + 1]) * ip[kk + 1];
                v.z = (v.z - mp[kk + 2]) * ip[kk + 2];
                v.w = (v.w - mp[kk + 3]) * ip[kk + 3];
                av[i][h] = v;
            }
        }
    };
    auto stsA = [&](int buf) {
        #pragma unroll
        for (int i = 0; i < 2; i++) {
            int p = tid + i * 256;
            int row = p >> 2, kq = p & 3;
            uint4 u;
            u.x = pkh2(__float2half_rn(av[i][0].x), __float2half_rn(av[i][0].y));
            u.y = pkh2(__float2half_rn(av[i][0].z), __float2half_rn(av[i][0].w));
            u.z = pkh2(__float2half_rn(av[i][1].x), __float2half_rn(av[i][1].y));
            u.w = pkh2(__float2half_rn(av[i][1].z), __float2half_rn(av[i][1].w));
            *(uint4*)(sm + buf * STAGE + row * PITCH + kq * 16) = u;
        }
    };
    auto cpB = [&](int c, int buf) {
        #pragma unroll
        for (int i = 0; i < 2; i++) {
            int s = tid + i * 256;
            int n = s >> 2, seg = s & 3;
            CP16(smu + buf * STAGE + CHNK + n * PITCH + seg * 16,
                 Bp + (size_t)n * 160 + c * 32 + seg * 8);
        }
    };

    int r = lane & 7, q = lane >> 3;
    uint32_t a_off[2], b_off[4], ws_off[4];
    #pragma unroll
    for (int mt = 0; mt < 2; mt++)
        a_off[mt] = (uint32_t)((wm * 32 + mt * 16 + (q & 1) * 8 + r) * PITCH + (q >> 1) * 16);
    #pragma unroll
    for (int np = 0; np < 4; np++) {
        uint32_t rb = (uint32_t)((wn * 64 + np * 16 + (q >> 1) * 8 + r) * PITCH + (q & 1) * 16);
        b_off[np]  = CHNK + rb;
        ws_off[np] = WSOFF + rb;
    }

    float acc[2][8][4];
    #pragma unroll
    for (int mt = 0; mt < 2; mt++)
        #pragma unroll
        for (int nt = 0; nt < 8; nt++)
            #pragma unroll
            for (int i = 0; i < 4; i++) acc[mt][nt][i] = 0.f;

    loadA(0); cpB(0, 0); CPCOMMIT();
    const int nch = 5;
    for (int c = 0; c < nch; c++) {
        int buf = c & 1;
        if (c + 1 < nch) { cpB(c + 1, buf ^ 1); CPCOMMIT(); }
        stsA(buf);
        if (c + 1 < nch) { loadA(c + 1); CPWAIT1(); }
        else             { CPWAIT0(); }
        __syncthreads();
        uint32_t bb = smu + buf * STAGE;
        #pragma unroll
        for (int ks = 0; ks < 2; ks++) {
            uint32_t af[2][4], bf[4][4];
            #pragma unroll
            for (int mt = 0; mt < 2; mt++) ldsm4(af[mt], bb + a_off[mt] + ks * 32);
            #pragma unroll
            for (int np = 0; np < 4; np++) ldsm4(bf[np], bb + b_off[np] + ks * 32);
            #pragma unroll
            for (int mt = 0; mt < 2; mt++)
                #pragma unroll
                for (int nt = 0; nt < 8; nt++)
                    mma16816(acc[mt][nt], af[mt], &bf[nt >> 1][(nt & 1) * 2]);
        }
        __syncthreads();
    }

    int g = lane >> 2, tig = lane & 3;

    #pragma unroll
    for (int mt = 0; mt < 2; mt++) {
        int row = wm * 32 + mt * 16 + g;
        #pragma unroll
        for (int nt = 0; nt < 8; nt++) {
            int col = wn * 64 + nt * 8 + 2 * tig;
            float b0 = enc_b[a * 128 + col], b1 = enc_b[a * 128 + col + 1];
            float v0 = lrelu(acc[mt][nt][0] + b0), v1 = lrelu(acc[mt][nt][1] + b1);
            float v2 = lrelu(acc[mt][nt][2] + b0), v3 = lrelu(acc[mt][nt][3] + b1);
            uint32_t tadr = (uint32_t)((col >> 5) * CHNK + row * PITCH + (col & 31) * 2);
            *(__half2*)(sm + tadr)             = __floats2half2_rn(v0, v1);
            *(__half2*)(sm + tadr + 8 * PITCH) = __floats2half2_rn(v2, v3);
        }
    }
    __syncthreads();

    tile_store(sm, 0, CHNK, 128, saout, (size_t)a * Bsz + m0);

    float a2[2][8][4];
    #pragma unroll
    for (int mt = 0; mt < 2; mt++)
        #pragma unroll
        for (int nt = 0; nt < 8; nt++)
            #pragma unroll
            for (int i = 0; i < 4; i++) a2[mt][nt][i] = 0.f;
    #pragma unroll
    for (int ks = 0; ks < 8; ks++) {
        uint32_t coff = (uint32_t)((ks >> 1) * CHNK + (ks & 1) * 32);
        uint32_t af[2][4], bf[4][4];
        #pragma unroll
        for (int mt = 0; mt < 2; mt++) ldsm4(af[mt], smu + a_off[mt] + coff);
        #pragma unroll
        for (int np = 0; np < 4; np++) ldsm4(bf[np], smu + ws_off[np] + coff);
        #pragma unroll
        for (int mt = 0; mt < 2; mt++)
            #pragma unroll
            for (int nt = 0; nt < 8; nt++)
                mma16816(a2[mt][nt], af[mt], &bf[nt >> 1][(nt & 1) * 2]);
    }
    __syncthreads();
    #pragma unroll
    for (int mt = 0; mt < 2; mt++) {
        int row = wm * 32 + mt * 16 + g;
        #pragma unroll
        for (int nt = 0; nt < 8; nt++) {
            int col = wn * 64 + nt * 8 + 2 * tig;
            uint32_t tadr = (uint32_t)(WSOFF + (col >> 5) * CHNK + row * PITCH + (col & 31) * 2);
            *(__half2*)(sm + tadr)             = __floats2half2_rn(a2[mt][nt][0], a2[mt][nt][1]);
            *(__half2*)(sm + tadr + 8 * PITCH) = __floats2half2_rn(a2[mt][nt][2], a2[mt][nt][3]);
        }
    }
    __syncthreads();
    tile_store(sm, WSOFF, CHNK, 128, selsout, (size_t)a * Bsz + m0);
}

// ---------------- a_enc + keys + vals body ----------------
#define BSOFF 40960
#define KVST  61440
#define KVCH  5120
__device__ __forceinline__ void aenc_kv_body(
    char* sm, uint32_t smu,
    const float* __restrict__ actions,
    const __half* __restrict__ Baenc, const float* __restrict__ aenc_b,
    const __half* __restrict__ Wkp, const __half* __restrict__ Wvp,
    const float* __restrict__ valb,
    __half* __restrict__ keysh, __half* __restrict__ valsh) {

    int tid = threadIdx.x, lane = tid & 31, wid = tid >> 5;
    int wm = wid & 3, wn = wid >> 2;
    int a = blockIdx.z, m0 = blockIdx.x * 128;

    const float* mp = g_mean + a * 160;
    const float* ip = g_istd + a * 160;
    size_t abo = (size_t)a * Bsz * 32;
    const __half* Bp = Baenc + (size_t)a * 128 * 32;

    #pragma unroll
    for (int i = 0; i < 2; i++) {
        int s = tid + i * 256;
        int n = s >> 2, seg = s & 3;
        CP16(smu + BSOFF + n * PITCH + seg * 16, Wkp + (size_t)n * 128 + seg * 8);
    }
    CPCOMMIT();

    float4 av[2][2];
    #pragma unroll
    for (int i = 0; i < 2; i++) {
        int p = tid + i * 256;
        int row = p >> 2, kq = p & 3;
        #pragma unroll
        for (int h = 0; h < 2; h++) {
            int kk = kq * 8 + h * 4;
            float4 v = *(const float4*)(actions + abo + (size_t)(m0 + row) * 32 + kk);
            v.x = (v.x - mp[128 + kk]) * ip[128 + kk];
            v.y = (v.y - mp[129 + kk]) * ip[129 + kk];
            v.z = (v.z - mp[130 + kk]) * ip[130 + kk];
            v.w = (v.w - mp[131 + kk]) * ip[131 + kk];
            av[i][h] = v;
        }
    }
    #pragma unroll
    for (int i = 0; i < 2; i++) {
        int s = tid + i * 256;
        int n = s >> 2, seg = s & 3;
        CP16(smu + CHNK + n * PITCH + seg * 16, Bp + (size_t)n * 32 + seg * 8);
    }
    CPCOMMIT();
    #pragma unroll
    for (int i = 0; i < 2; i++) {
        int p = tid + i * 256;
        int row = p >> 2, kq = p & 3;
        uint4 u;
        u.x = pkh2(__float2half_rn(av[i][0].x), __float2half_rn(av[i][0].y));
        u.y = pkh2(__float2half_rn(av[i][0].z), __float2half_rn(av[i][0].w));
        u.z = pkh2(__float2half_rn(av[i][1].x), __float2half_rn(av[i][1].y));
        u.w = pkh2(__float2half_rn(av[i][1].z), __float2half_rn(av[i][1].w));
        *(uint4*)(sm + row * PITCH + kq * 16) = u;
    }
    CPWAIT0();
    __syncthreads();

    int r = lane & 7, q = lane >> 3;
    uint32_t a_off[2], b_off[4], bs_off[4];
    #pragma unroll
    for (int mt = 0; mt < 2; mt++)
        a_off[mt] = (uint32_t)((wm * 32 + mt * 16 + (q & 1) * 8 + r) * PITCH + (q >> 1) * 16);
    #pragma unroll
    for (int np = 0; np < 4; np++) {
        uint32_t rb = (uint32_t)((wn * 64 + np * 16 + (q >> 1) * 8 + r) * PITCH + (q & 1) * 16);
        b_off[np]  = CHNK + rb;
        bs_off[np] = BSOFF + rb;
    }

    float acc[2][8][4];
    #pragma unroll
    for (int mt = 0; mt < 2; mt++)
        #pragma unroll
        for (int nt = 0; nt < 8; nt++)
            #pragma unroll
            for (int i = 0; i < 4; i++) acc[mt][nt][i] = 0.f;

    #pragma unroll
    for (int ks = 0; ks < 2; ks++) {
        uint32_t af[2][4], bf[4][4];
        #pragma unroll
        for (int mt = 0; mt < 2; mt++) ldsm4(af[mt], smu + a_off[mt] + ks * 32);
        #pragma unroll
        for (int np = 0; np < 4; np++) ldsm4(bf[np], smu + b_off[np] + ks * 32);
        #pragma unroll
        for (int mt = 0; mt < 2; mt++)
            #pragma unroll
            for (int nt = 0; nt < 8; nt++)
                mma16816(acc[mt][nt], af[mt], &bf[nt >> 1][(nt & 1) * 2]);
    }
    __syncthreads();

    int g = lane >> 2, tig = lane & 3;

    #pragma unroll
    for (int mt = 0; mt < 2; mt++) {
        int row = wm * 32 + mt * 16 + g;
        #pragma unroll
        for (int nt = 0; nt < 8; nt++) {
            int col = wn * 64 + nt * 8 + 2 * tig;
            float b0 = aenc_b[a * 128 + col], b1 = aenc_b[a * 128 + col + 1];
            float v0 = lrelu(acc[mt][nt][0] + b0), v1 = lrelu(acc[mt][nt][1] + b1);
            float v2 = lrelu(acc[mt][nt][2] + b0), v3 = lrelu(acc[mt][nt][3] + b1);
            uint32_t tadr = (uint32_t)((col >> 5) * CHNK + row * PITCH + (col & 31) * 2);
            *(__half2*)(sm + tadr)             = __floats2half2_rn(v0, v1);
            *(__half2*)(sm + tadr + 8 * PITCH) = __floats2half2_rn(v2, v3);
            acc[mt][nt][0] = 0.f; acc[mt][nt][1] = 0.f;
            acc[mt][nt][2] = 0.f; acc[mt][nt][3] = 0.f;
        }
    }
    __syncthreads();

    auto cpB2 = [&](int c, int buf) {
        const __half* src = (c < 4) ? Wkp : Wvp;
        int cc = c & 3;
        #pragma unroll
        for (int i = 0; i < 2; i++) {
            int s = tid + i * 256;
            int n = s >> 2, seg = s & 3;
            CP16(smu + BSOFF + buf * CHNK + n * PITCH + seg * 16,
                 src + (size_t)n * 128 + cc * 32 + seg * 8);
        }
    };

    for (int c = 0; c < 8; c++) {
        int buf = c & 1;
        if (c + 1 < 8) { cpB2(c + 1, buf ^ 1); CPCOMMIT(); CPWAIT1(); }
        else           { CPWAIT0(); }
        __syncthreads();
        #pragma unroll
        for (int ks = 0; ks < 2; ks++) {
            uint32_t coffA = (uint32_t)((c & 3) * CHNK + ks * 32);
            uint32_t af[2][4], bf[4][4];
            #pragma unroll
            for (int mt = 0; mt < 2; mt++) ldsm4(af[mt], smu + a_off[mt] + coffA);
            #pragma unroll
            for (int np = 0; np < 4; np++) ldsm4(bf[np], smu + bs_off[np] + buf * CHNK + ks * 32);
            #pragma unroll
            for (int mt = 0; mt < 2; mt++)
                #pragma unroll
                for (int nt = 0; nt < 8; nt++)
                    mma16816(acc[mt][nt], af[mt], &bf[nt >> 1][(nt & 1) * 2]);
        }
        __syncthreads();

        if (c == 3 || c == 7) {
            bool isv = (c == 7);
            __half* outp = isv ? valsh : keysh;
            #pragma unroll
            for (int pass = 0; pass < 2; pass++) {
                if ((wm >> 1) == pass) {
                    int lbase = (wm & 1) * 32;
                    #pragma unroll
                    for (int mt = 0; mt < 2; mt++) {
                        int lrow = lbase + mt * 16 + g;
                        #pragma unroll
                        for (int nt = 0; nt < 8; nt++) {
                            int col = wn * 64 + nt * 8 + 2 * tig;
                            float v0 = acc[mt][nt][0], v1 = acc[mt][nt][1];
                            float v2 = acc[mt][nt][2], v3 = acc[mt][nt][3];
                            if (isv) {
                                float b0 = valb[col], b1 = valb[col + 1];
                                v0 = lrelu(v0 + b0); v1 = lrelu(v1 + b1);
                                v2 = lrelu(v2 + b0); v3 = lrelu(v3 + b1);
                            }
                            uint32_t tadr = (uint32_t)(KVST + (col >> 5) * KVCH
                                            + lrow * PITCH + (col & 31) * 2);
                            *(__half2*)(sm + tadr)             = __floats2half2_rn(v0, v1);
                            *(__half2*)(sm + tadr + 8 * PITCH) = __floats2half2_rn(v2, v3);
                        }
                    }
                }
                __syncthreads();
                tile_store(sm, KVST, KVCH, 64, outp, (size_t)a * Bsz + m0 + pass * 64);
                __syncthreads();
            }
            if (!isv) {
                #pragma unroll
                for (int mt = 0; mt < 2; mt++)
                    #pragma unroll
                    for (int nt = 0; nt < 8; nt++)
                        #pragma unroll
                        for (int i = 0; i < 4; i++) acc[mt][nt][i] = 0.f;
            }
        }
    }
}

// ---------------- merged encoder launch ----------------
__global__ __launch_bounds__(256, 2) void enc_k(
    const float* __restrict__ states, const float* __restrict__ actions,
    const __half* __restrict__ Benc, const float* __restrict__ enc_b,
    const __half* __restrict__ Wsp,
    __half* __restrict__ saout, __half* __restrict__ selsout,
    const __half* __restrict__ Baenc, const float* __restrict__ aenc_b,
    const __half* __restrict__ Wkp, const __half* __restrict__ Wvp,
    const float* __restrict__ valb,
    __half* __restrict__ keysh, __half* __restrict__ valsh) {

    extern __shared__ __align__(16) char sm[];
    uint32_t smu = smem_u32(sm);
    if (blockIdx.y == 0)
        sa_sels_body(sm, smu, states, actions, Benc, enc_b, Wsp, saout, selsout);
    else
        aenc_kv_body(sm, smu, actions, Baenc, aenc_b, Wkp, Wvp, valb, keysh, valsh);
}

// ---------------- c1 + q fused, K=256, 3-stage cp.async pipeline ----------------
__global__ __launch_bounds__(256, 2) void c1q_k(
    const __half* __restrict__ sah, const __half* __restrict__ att,
    const __half* __restrict__ Bc1, const float* __restrict__ c1_b,
    const float* __restrict__ c2w, const float* __restrict__ c2b,
    float* __restrict__ qout) {

    extern __shared__ __align__(16) char sm[];
    uint32_t smu = smem_u32(sm);
    int tid = threadIdx.x, lane = tid & 31, wid = tid >> 5;
    int wm = wid & 3, wn = wid >> 2;
    int a = blockIdx.z, m0 = blockIdx.x * 128;

    const char* Ap  = (const char*)(sah + (size_t)a * Bsz * 128);
    const char* Atp = (const char*)(att + (size_t)a * Bsz * 128);
    const __half* Bpp = Bc1 + (size_t)a * 128 * 256;

    auto cpA = [&](int c, int buf) {
        #pragma unroll
        for (int i = 0; i < 2; i++) {
            int p = tid + i * 256;
            int row = p >> 2, seg = p & 3;
            const char* g;
            if (c < 4) g = Ap + (size_t)(m0 + row) * 256 + c * 64 + seg * 16;
            else       g = Atp + (size_t)(m0 + row) * 256 + (c - 4) * 64 + seg * 16;
            CP16(smu + buf * STAGE + row * PITCH + seg * 16, g);
        }
    };
    auto cpB = [&](int c, int buf) {
        #pragma unroll
        for (int i = 0; i < 2; i++) {
            int s = tid + i * 256;
            int n = s >> 2, seg = s & 3;
            CP16(smu + buf * STAGE + CHNK + n * PITCH + seg * 16,
                 Bpp + (size_t)n * 256 + c * 32 + seg * 8);
        }
    };

    int r = lane & 7, q = lane >> 3;
    uint32_t a_off[2], b_off[4];
    #pragma unroll
    for (int mt = 0; mt < 2; mt++)
        a_off[mt] = (uint32_t)((wm * 32 + mt * 16 + (q & 1) * 8 + r) * PITCH + (q >> 1) * 16);
    #pragma unroll
    for (int np = 0; np < 4; np++)
        b_off[np] = (uint32_t)(CHNK + (wn * 64 + np * 16 + (q >> 1) * 8 + r) * PITCH + (q & 1) * 16);

    float acc[2][8][4];
    #pragma unroll
    for (int mt = 0; mt < 2; mt++)
        #pragma unroll
        for (int nt = 0; nt < 8; nt++)
            #pragma unroll
            for (int i = 0; i < 4; i++) acc[mt][nt][i] = 0.f;

    cpA(0, 0); cpB(0, 0); CPCOMMIT();
    cpA(1, 1); cpB(1, 1); CPCOMMIT();
    const int nch = 8;
    int buf = 0;
    for (int c = 0; c < nch; c++) {
        if (c + 2 < nch) {
            int nb = (buf + 2) % 3;
            cpA(c + 2, nb); cpB(c + 2, nb); CPCOMMIT();
            CPWAIT2();
        } else if (c + 1 < nch) {
            CPWAIT1();
        } else {
            CPWAIT0();
        }
        __syncthreads();
        uint32_t bb = smu + buf * STAGE;
        #pragma unroll
        for (int ks = 0; ks < 2; ks++) {
            uint32_t af[2][4], bf[4][4];
            #pragma unroll
            for (int mt = 0; mt < 2; mt++) ldsm4(af[mt], bb + a_off[mt] + ks * 32);
            #pragma unroll
            for (int np = 0; np < 4; np++) ldsm4(bf[np], bb + b_off[np] + ks * 32);
            #pragma unroll
            for (int mt = 0; mt < 2; mt++)
                #pragma unroll
                for (int nt = 0; nt < 8; nt++)
                    mma16816(acc[mt][nt], af[mt], &bf[nt >> 1][(nt & 1) * 2]);
        }
        __syncthreads();
        buf = (buf + 1) % 3;
    }

    int g = lane >> 2, tig = lane & 3;
    float qp[4] = {0.f, 0.f, 0.f, 0.f};
    #pragma unroll
    for (int mt = 0; mt < 2; mt++)
        #pragma unroll
        for (int nt = 0; nt < 8; nt++) {
            int col = wn * 64 + nt * 8 + 2 * tig;
            float b0 = c1_b[a * 128 + col], b1 = c1_b[a * 128 + col + 1];
            float w0 = c2w[a * 128 + col], w1 = c2w[a * 128 + col + 1];
            qp[mt * 2]     += lrelu(acc[mt][nt][0] + b0) * w0 + lrelu(acc[mt][nt][1] + b1) * w1;
            qp[mt * 2 + 1] += lrelu(acc[mt][nt][2] + b0) * w0 + lrelu(acc[mt][nt][3] + b1) * w1;
        }
    #pragma unroll
    for (int j = 0; j < 4; j++) {
        qp[j] += __shfl_xor_sync(0xffffffffu, qp[j], 1);
        qp[j] += __shfl_xor_sync(0xffffffffu, qp[j], 2);
    }
    __syncthreads();
    float* qsm = (float*)sm;
    if (tig == 0) {
        #pragma unroll
        for (int j = 0; j < 4; j++) {
            int rl = wm * 32 + (j >> 1) * 16 + (j & 1) * 8 + g;
            qsm[rl * 2 + wn] = qp[j];
        }
    }
    __syncthreads();
    if (tid < 128)
        qout[(size_t)a * Bsz + m0 + tid] = qsm[tid * 2] + qsm[tid * 2 + 1] + c2b[a];
}

// ---------------- attention: proven structure, hfma2 math ----------
#define APITCH 36
__global__ __launch_bounds__(128) void attn_k() {
    __shared__ __half sS[128 * APITCH];
    __shared__ __half sK[128 * APITCH];
    int t = threadIdx.x;
    int b0 = blockIdx.x * 16;
    int bl = t >> 3, iq = t & 7;

    for (int kh = 0; kh < 4; kh++) {
        __syncthreads();
        {
            int lbl = t >> 3, ag = t & 7;
            size_t off = ((size_t)ag * Bsz + b0 + lbl) * 128 + kh * 32;
            const uint2* ps = (const uint2*)(g_selsh + off);
            const uint2* pk = (const uint2*)(g_keysh + off);
            uint2* ds = (uint2*)(sS + (lbl * 8 + ag) * APITCH);
            uint2* dk = (uint2*)(sK + (lbl * 8 + ag) * APITCH);
            #pragma unroll
            for (int j = 0; j < 8; j++) { ds[j] = ps[j]; dk[j] = pk[j]; }
        }
        __syncthreads();

        // own sels row as 16 packed half2 regs
        uint32_t sv2[16];
        {
            const uint32_t* p = (const uint32_t*)(sS + (bl * 8 + iq) * APITCH);
            #pragma unroll
            for (int d = 0; d < 16; d++) sv2[d] = p[d];
        }
        float pj[8];
        #pragma unroll
        for (int j = 0; j < 8; j++) {
            const uint32_t* p = (const uint32_t*)(sK + (bl * 8 + j) * APITCH);
            __half2 hacc = __floats2half2_rn(0.f, 0.f);
            #pragma unroll
            for (int d = 0; d < 16; d++)
                hacc = __hfma2(*(const __half2*)&sv2[d], *(const __half2*)&p[d], hacc);
            float2 f = __half22float2(hacc);
            pj[j] = (f.x + f.y) * 0.17677669529663687f;
        }
        float mx = -1e30f;
        #pragma unroll
        for (int j = 0; j < 8; j++) if (j != iq) mx = fmaxf(mx, pj[j]);
        float sum = 0.f;
        #pragma unroll
        for (int j = 0; j < 8; j++) {
            pj[j] = (j == iq) ? 0.f : __expf(pj[j] - mx);
            sum += pj[j];
        }
        float inv = 1.f / sum;

        __syncthreads();
        {
            int lbl = t >> 3, ag = t & 7;
            size_t off = ((size_t)ag * Bsz + b0 + lbl) * 128 + kh * 32;
            const uint2* pv = (const uint2*)(g_valsh + off);
            uint2* ds = (uint2*)(sS + (lbl * 8 + ag) * APITCH);
            #pragma unroll
            for (int j = 0; j < 8; j++) ds[j] = pv[j];
        }
        __syncthreads();

        // weighted sum in half2 accumulators (16 regs, half the FMA)
        uint32_t ov2[16];
        #pragma unroll
        for (int d = 0; d < 16; d++) ov2[d] = 0u;
        #pragma unroll
        for (int j = 0; j < 8; j++) {
            __half wh = __float2half_rn(pj[j] * inv);
            __half2 wh2 = __halves2half2(wh, wh);
            const uint32_t* p = (const uint32_t*)(sS + (bl * 8 + j) * APITCH);
            #pragma unroll
            for (int d = 0; d < 16; d++) {
                __half2 res = __hfma2(wh2, *(const __half2*)&p[d], *(__half2*)&ov2[d]);
                ov2[d] = *(uint32_t*)&res;
            }
        }
        __half* dst = g_atth + ((size_t)iq * Bsz + b0 + bl) * 128 + kh * 32;
        #pragma unroll
        for (int d4 = 0; d4 < 4; d4++) {
            uint4 u;
            u.x = ov2[d4 * 4];     u.y = ov2[d4 * 4 + 1];
            u.z = ov2[d4 * 4 + 2]; u.w = ov2[d4 * 4 + 3];
            *(uint4*)(dst + d4 * 8) = u;
        }
    }
}

// ---------------- launch ----------------
extern "C" void kernel_launch(void* const* d_in, const int* in_sizes, int n_in,
                              void* d_out, int out_size) {
    const float* states = (const float*)d_in[0];
    const float* actions= (const float*)d_in[1];
    const float* enc_w  = (const float*)d_in[2];
    const float* enc_b  = (const float*)d_in[3];
    const float* aenc_w = (const float*)d_in[4];
    const float* aenc_b = (const float*)d_in[5];
    const float* key_w  = (const float*)d_in[6];
    const float* sel_w  = (const float*)d_in[7];
    const float* val_w  = (const float*)d_in[8];
    const float* val_b  = (const float*)d_in[9];
    const float* c1_w   = (const float*)d_in[10];
    const float* c1_b   = (const float*)d_in[11];
    const float* c2_w   = (const float*)d_in[12];
    const float* c2_b   = (const float*)d_in[13];
    float* out = (float*)d_out;

    void *p_sah, *p_keysh, *p_selsh, *p_valsh, *p_atth;
    void *p_Benc, *p_Baenc, *p_Bc1, *p_Wkp, *p_Wsp, *p_Wvp;
    cudaGetSymbolAddress(&p_sah,  g_sah);
    cudaGetSymbolAddress(&p_keysh,g_keysh);
    cudaGetSymbolAddress(&p_selsh,g_selsh);
    cudaGetSymbolAddress(&p_valsh,g_valsh);
    cudaGetSymbolAddress(&p_atth, g_atth);
    cudaGetSymbolAddress(&p_Benc, g_Benc);
    cudaGetSymbolAddress(&p_Baenc,g_Baenc);
    cudaGetSymbolAddress(&p_Bc1,  g_Bc1);
    cudaGetSymbolAddress(&p_Wkp,  g_Wkp);
    cudaGetSymbolAddress(&p_Wsp,  g_Wsp);
    cudaGetSymbolAddress(&p_Wvp,  g_Wvp);

    cudaFuncSetAttribute(enc_k, cudaFuncAttributeMaxDynamicSharedMemorySize, 81920);
    cudaFuncSetAttribute(c1q_k, cudaFuncAttributeMaxDynamicSharedMemorySize, 61440);

    prep_k<<<504, 320>>>(states, actions, enc_w, aenc_w, c1_w, key_w, sel_w, val_w);
    bn_final_k<<<8, 160>>>();
    enc_k<<<dim3(256, 2, 8), 256, 81920>>>(
        states, actions,
        (const __half*)p_Benc, enc_b, (const __half*)p_Wsp,
        (__half*)p_sah, (__half*)p_selsh,
        (const __half*)p_Baenc, aenc_b,
        (const __half*)p_Wkp, (const __half*)p_Wvp, val_b,
        (__half*)p_keysh, (__half*)p_valsh);
    attn_k<<<Bsz / 16, 128>>>();
    c1q_k<<<dim3(256, 1, 8), 256, 61440>>>((const __half*)p_sah, (const __half*)p_atth,
                                           (const __half*)p_Bc1, c1_b, c2_w, c2_b, out);
}